// round 15
// baseline (speedup 1.0000x reference)
#include <cuda_runtime.h>
#include <cuda_fp16.h>
#include <cuda_fp8.h>

#define B_   2048
#define L_   64
#define N_   1024
#define E_   32
#define SE_  16
#define F_   8
#define NSH  56      // E + F + SE
#define NF   59      // NSH + 3
#define S_   20
#define T    256
#define JP   (NSH / 2)   // 28 j-pairs
#define PF   4           // prefetched l-slices via cp.async

// fp8 conv weights, packed j-pairs: g_convT8[jp][n][2] = {w[2jp][n], w[2jp+1][n]}  (56 KB)
__device__ __align__(256) __nv_fp8_storage_t g_convT8[JP * N_ * 2];
// fp32 tail rows 56..58 of conv_w (transposed): [w56 | w57 | w58]
__device__ __align__(256) float g_tail[3 * N_];

// prep: conv_w transpose/convert only (236 blocks x 256 == NF*N_ exactly)
__global__ __launch_bounds__(T) void prep_kernel(const float* __restrict__ conv_w)
{
    const int t = blockIdx.x * blockDim.x + threadIdx.x;
    int n = t / NF;
    int j = t - n * NF;
    float v = conv_w[t];
    if (j < NSH)
        g_convT8[(j >> 1) * (N_ * 2) + n * 2 + (j & 1)] =
            __nv_cvt_float_to_fp8(v, __NV_SATFINITE, __NV_E4M3);
    else
        g_tail[(j - NSH) * N_ + n] = v;
}

// single-row phase A: conv dot + row-independent terms -> s_base
__device__ __forceinline__ void phase_a(
    int b, int n0, const float* s_sh, float* s_base,
    const float* __restrict__ x_dist, const float* __restrict__ x_markov,
    const float* __restrict__ conv_b, const float* __restrict__ fc1_b)
{
    float d0 = 0.f, d1 = 0.f, d2 = 0.f, d3 = 0.f;
    #pragma unroll 4
    for (int jp = 0; jp < JP; ++jp) {
        uint2 wv = *(const uint2*)(&g_convT8[jp * (N_ * 2) + n0 * 2]);
        __half2_raw h0 = __nv_cvt_fp8x2_to_halfraw2(
            (__nv_fp8x2_storage_t)(wv.x & 0xFFFFu), __NV_E4M3);
        __half2_raw h1 = __nv_cvt_fp8x2_to_halfraw2(
            (__nv_fp8x2_storage_t)(wv.x >> 16), __NV_E4M3);
        __half2_raw h2 = __nv_cvt_fp8x2_to_halfraw2(
            (__nv_fp8x2_storage_t)(wv.y & 0xFFFFu), __NV_E4M3);
        __half2_raw h3 = __nv_cvt_fp8x2_to_halfraw2(
            (__nv_fp8x2_storage_t)(wv.y >> 16), __NV_E4M3);
        float2 f0 = __half22float2(*(const __half2*)&h0);
        float2 f1 = __half22float2(*(const __half2*)&h1);
        float2 f2 = __half22float2(*(const __half2*)&h2);
        float2 f3 = __half22float2(*(const __half2*)&h3);
        float ha = s_sh[2 * jp], hb = s_sh[2 * jp + 1];
        d0 = fmaf(ha, f0.x, fmaf(hb, f0.y, d0));
        d1 = fmaf(ha, f1.x, fmaf(hb, f1.y, d1));
        d2 = fmaf(ha, f2.x, fmaf(hb, f2.y, d2));
        d3 = fmaf(ha, f3.x, fmaf(hb, f3.y, d3));
    }

    float4 w56 = *(const float4*)(&g_tail[0 * N_ + n0]);
    float4 w57 = *(const float4*)(&g_tail[1 * N_ + n0]);
    float4 w58 = *(const float4*)(&g_tail[2 * N_ + n0]);
    float4 cb  = *(const float4*)(&conv_b[n0]);
    float4 xd  = *(const float4*)(&x_dist[n0]);
    float  fb  = *fc1_b;

    size_t gbase = (size_t)b * N_ + (size_t)n0;
    float4 xm = *(const float4*)(&x_markov[gbase]);

    float4 sb;
    sb.x = d0 + xm.x * w58.x + xd.x * w57.x + cb.x + fb * w56.x;
    sb.y = d1 + xm.y * w58.y + xd.y * w57.y + cb.y + fb * w56.y;
    sb.z = d2 + xm.z * w58.z + xd.z * w57.z + cb.z + fb * w56.z;
    sb.w = d3 + xm.w * w58.w + xd.w * w57.w + cb.w + fb * w56.w;
    *(float4*)(&s_base[n0]) = sb;
}

// fused 1-row kernel: cp.async prefetch -> gather+phase A (DRAM fed by prefetch)
//                     -> smem slices -> LDG stream -> softmax
__global__ __launch_bounds__(T, 8) void main_kernel(
    const float* __restrict__ x,          // [B, L, N]
    const float* __restrict__ x_dist,     // [N]
    const float* __restrict__ x_features, // [B, F]
    const float* __restrict__ x_markov,   // [B, N]
    const int*   __restrict__ stops,      // [B, S]
    const int*   __restrict__ x_week,     // [B]
    const int*   __restrict__ x_mask,     // [B, N]
    const float* __restrict__ stop_emb,   // [N, SE]
    const float* __restrict__ week_emb,   // [NW, E]
    const float* __restrict__ conv_b,     // [N]
    const float* __restrict__ fc1_w,      // [L]
    const float* __restrict__ fc1_b,      // scalar
    float*       __restrict__ out)        // [B, N]
{
    __shared__ float s_stage[PF][N_];   // 16 KB prefetch staging
    __shared__ float s_w[L_];
    __shared__ float s_sh[NSH];
    __shared__ float s_red[8];
    __shared__ float s_base[N_];        // row-independent part of logits

    const int tid  = threadIdx.x;
    const int lane = tid & 31;
    const int warp = tid >> 5;
    const int b    = blockIdx.x;
    const int n0   = tid * 4;

    const float* xrow = x + (size_t)b * (L_ * N_);

    // ---- 1. issue prefetch of slices 0..PF-1 (no registers held; own-slot only) ----
    #pragma unroll
    for (int p = 0; p < PF; ++p) {
        unsigned sa = (unsigned)__cvta_generic_to_shared(&s_stage[p][n0]);
        const float* ga = xrow + (size_t)p * N_ + n0;
        asm volatile("cp.async.cg.shared.global [%0], [%1], 16;"
                     :: "r"(sa), "l"(ga) : "memory");
        asm volatile("cp.async.commit_group;" ::: "memory");
    }

    // ---- 2. gather shared features + fc1 weights (DRAM fed by prefetch) ----
    if (tid < L_) s_w[tid] = fc1_w[tid];
    if (tid < NSH) {
        int j = tid;
        float v;
        if (j < E_) {
            v = week_emb[x_week[b] * E_ + j];
        } else if (j < E_ + F_) {
            v = x_features[b * F_ + (j - E_)];
        } else {
            int c = j - E_ - F_;
            float s = 0.f;
            #pragma unroll
            for (int st = 0; st < S_; ++st)
                s += stop_emb[stops[b * S_ + st] * SE_ + c];
            v = s;
        }
        s_sh[j] = v;
    }
    __syncthreads();

    // ---- 3. phase A for ALL blocks (overlapped with in-flight prefetch) ----
    phase_a(b, n0, s_sh, s_base, x_dist, x_markov, conv_b, fc1_b);

    // ---- 4. stream: smem slices then plain LDG (R14 loop shape) ----
    float4 acc = make_float4(0.f, 0.f, 0.f, 0.f);

    asm volatile("cp.async.wait_group 0;" ::: "memory");  // instant: arrived during phase A
    #pragma unroll
    for (int p = 0; p < PF; ++p) {
        float4 xv = *(const float4*)(&s_stage[p][n0]);
        float wl = s_w[p];
        acc.x = fmaf(wl, xv.x, acc.x);
        acc.y = fmaf(wl, xv.y, acc.y);
        acc.z = fmaf(wl, xv.z, acc.z);
        acc.w = fmaf(wl, xv.w, acc.w);
    }

    {
        const float4* xb = (const float4*)xrow + tid;
        #pragma unroll 4
        for (int l = PF; l < L_; ++l) {
            float4 xv = xb[(size_t)l * (N_ / 4)];
            float wl = s_w[l];
            acc.x = fmaf(wl, xv.x, acc.x);
            acc.y = fmaf(wl, xv.y, acc.y);
            acc.z = fmaf(wl, xv.z, acc.z);
            acc.w = fmaf(wl, xv.w, acc.w);
        }
    }

    // ---- 5. logits + log_softmax + mask + store ----
    {
        float4 sb  = *(const float4*)(&s_base[n0]);
        float4 w56 = *(const float4*)(&g_tail[0 * N_ + n0]);  // L2-resident

        float lg0 = sb.x + acc.x * w56.x;
        float lg1 = sb.y + acc.y * w56.y;
        float lg2 = sb.z + acc.z * w56.z;
        float lg3 = sb.w + acc.w * w56.w;

        float m = fmaxf(fmaxf(lg0, lg1), fmaxf(lg2, lg3));
        #pragma unroll
        for (int off = 16; off > 0; off >>= 1)
            m = fmaxf(m, __shfl_xor_sync(0xffffffffu, m, off));
        if (lane == 0) s_red[warp] = m;
        __syncthreads();
        m = s_red[0];
        #pragma unroll
        for (int w = 1; w < 8; ++w) m = fmaxf(m, s_red[w]);
        __syncthreads();

        float s = __expf(lg0 - m) + __expf(lg1 - m) + __expf(lg2 - m) + __expf(lg3 - m);
        #pragma unroll
        for (int off = 16; off > 0; off >>= 1)
            s += __shfl_xor_sync(0xffffffffu, s, off);
        if (lane == 0) s_red[warp] = s;
        __syncthreads();
        s = 0.f;
        #pragma unroll
        for (int w = 0; w < 8; ++w) s += s_red[w];
        float lse = m + __logf(s);

        size_t gb = (size_t)b * N_ + (size_t)n0;
        int4 mk = *(const int4*)(&x_mask[gb]);
        float4 o;
        o.x = mk.x ? -1e8f : (lg0 - lse);
        o.y = mk.y ? -1e8f : (lg1 - lse);
        o.z = mk.z ? -1e8f : (lg2 - lse);
        o.w = mk.w ? -1e8f : (lg3 - lse);
        *(float4*)(&out[gb]) = o;
    }
}

extern "C" void kernel_launch(void* const* d_in, const int* in_sizes, int n_in,
                              void* d_out, int out_size) {
    const float* x          = (const float*)d_in[0];
    const float* x_dist     = (const float*)d_in[1];
    const float* x_features = (const float*)d_in[2];
    const float* x_markov   = (const float*)d_in[3];
    const int*   stops      = (const int*)  d_in[4];
    const int*   x_week     = (const int*)  d_in[5];
    const int*   x_mask     = (const int*)  d_in[6];
    const float* stop_emb   = (const float*)d_in[7];
    const float* week_emb   = (const float*)d_in[8];
    const float* conv_w     = (const float*)d_in[9];
    const float* conv_b     = (const float*)d_in[10];
    const float* fc1_w      = (const float*)d_in[11];
    const float* fc1_b      = (const float*)d_in[12];
    float*       out        = (float*)d_out;

    prep_kernel<<<(NF * N_) / T, T>>>(conv_w);
    main_kernel<<<B_, T>>>(x, x_dist, x_features, x_markov, stops, x_week,
                           x_mask, stop_emb, week_emb, conv_b,
                           fc1_w, fc1_b, out);
}

// round 16
// speedup vs baseline: 1.0659x; 1.0659x over previous
#include <cuda_runtime.h>
#include <cuda_fp16.h>
#include <cuda_fp8.h>

#define B_   2048
#define L_   64
#define N_   1024
#define E_   32
#define SE_  16
#define F_   8
#define NSH  56      // E + F + SE
#define NF   59      // NSH + 3
#define S_   20
#define T    256
#define JP   (NSH / 2)   // 28 j-pairs

// fp8 conv weights, packed j-pairs: g_convT8[jp][n][2] = {w[2jp][n], w[2jp+1][n]}  (56 KB)
__device__ __align__(256) __nv_fp8_storage_t g_convT8[JP * N_ * 2];
// fp32 tail rows 56..58 of conv_w (transposed): [w56 | w57 | w58]
__device__ __align__(256) float g_tail[3 * N_];

// prep: conv_w transpose/convert only (236 blocks x 256 == NF*N_ exactly)
__global__ __launch_bounds__(T) void prep_kernel(const float* __restrict__ conv_w)
{
    const int t = blockIdx.x * blockDim.x + threadIdx.x;
    int n = t / NF;
    int j = t - n * NF;
    float v = conv_w[t];
    if (j < NSH)
        g_convT8[(j >> 1) * (N_ * 2) + n * 2 + (j & 1)] =
            __nv_cvt_float_to_fp8(v, __NV_SATFINITE, __NV_E4M3);
    else
        g_tail[(j - NSH) * N_ + n] = v;
}

// single-row phase A: conv dot + row-independent terms -> s_base
__device__ __forceinline__ void phase_a(
    int b, int n0, const float* s_sh, float* s_base,
    const float* __restrict__ x_dist, const float* __restrict__ x_markov,
    const float* __restrict__ conv_b, const float* __restrict__ fc1_b)
{
    float d0 = 0.f, d1 = 0.f, d2 = 0.f, d3 = 0.f;
    #pragma unroll 7
    for (int jp = 0; jp < JP; ++jp) {
        uint2 wv = *(const uint2*)(&g_convT8[jp * (N_ * 2) + n0 * 2]);
        __half2_raw h0 = __nv_cvt_fp8x2_to_halfraw2(
            (__nv_fp8x2_storage_t)(wv.x & 0xFFFFu), __NV_E4M3);
        __half2_raw h1 = __nv_cvt_fp8x2_to_halfraw2(
            (__nv_fp8x2_storage_t)(wv.x >> 16), __NV_E4M3);
        __half2_raw h2 = __nv_cvt_fp8x2_to_halfraw2(
            (__nv_fp8x2_storage_t)(wv.y & 0xFFFFu), __NV_E4M3);
        __half2_raw h3 = __nv_cvt_fp8x2_to_halfraw2(
            (__nv_fp8x2_storage_t)(wv.y >> 16), __NV_E4M3);
        float2 f0 = __half22float2(*(const __half2*)&h0);
        float2 f1 = __half22float2(*(const __half2*)&h1);
        float2 f2 = __half22float2(*(const __half2*)&h2);
        float2 f3 = __half22float2(*(const __half2*)&h3);
        float ha = s_sh[2 * jp], hb = s_sh[2 * jp + 1];
        d0 = fmaf(ha, f0.x, fmaf(hb, f0.y, d0));
        d1 = fmaf(ha, f1.x, fmaf(hb, f1.y, d1));
        d2 = fmaf(ha, f2.x, fmaf(hb, f2.y, d2));
        d3 = fmaf(ha, f3.x, fmaf(hb, f3.y, d3));
    }

    float4 w56 = *(const float4*)(&g_tail[0 * N_ + n0]);
    float4 w57 = *(const float4*)(&g_tail[1 * N_ + n0]);
    float4 w58 = *(const float4*)(&g_tail[2 * N_ + n0]);
    float4 cb  = *(const float4*)(&conv_b[n0]);
    float4 xd  = *(const float4*)(&x_dist[n0]);
    float  fb  = *fc1_b;

    size_t gbase = (size_t)b * N_ + (size_t)n0;
    float4 xm = *(const float4*)(&x_markov[gbase]);

    float4 sb;
    sb.x = d0 + xm.x * w58.x + xd.x * w57.x + cb.x + fb * w56.x;
    sb.y = d1 + xm.y * w58.y + xd.y * w57.y + cb.y + fb * w56.y;
    sb.z = d2 + xm.z * w58.z + xd.z * w57.z + cb.z + fb * w56.z;
    sb.w = d3 + xm.w * w58.w + xd.w * w57.w + cb.w + fb * w56.w;
    *(float4*)(&s_base[n0]) = sb;
}

// this row's shared features -> s_sh
__device__ __forceinline__ void gather_sh(
    int b, int tid, float* s_sh,
    const float* __restrict__ x_features, const int* __restrict__ stops,
    const int* __restrict__ x_week, const float* __restrict__ stop_emb,
    const float* __restrict__ week_emb)
{
    if (tid < NSH) {
        int j = tid;
        float v;
        if (j < E_) {
            v = week_emb[x_week[b] * E_ + j];
        } else if (j < E_ + F_) {
            v = x_features[b * F_ + (j - E_)];
        } else {
            int c = j - E_ - F_;
            float s = 0.f;
            #pragma unroll
            for (int st = 0; st < S_; ++st)
                s += stop_emb[stops[b * S_ + st] * SE_ + c];
            v = s;
        }
        s_sh[j] = v;
    }
}

// fused 1-row kernel, parity-staggered; gather placed off the stream's critical path
__global__ __launch_bounds__(T, 8) void main_kernel(
    const float* __restrict__ x,          // [B, L, N]
    const float* __restrict__ x_dist,     // [N]
    const float* __restrict__ x_features, // [B, F]
    const float* __restrict__ x_markov,   // [B, N]
    const int*   __restrict__ stops,      // [B, S]
    const int*   __restrict__ x_week,     // [B]
    const int*   __restrict__ x_mask,     // [B, N]
    const float* __restrict__ stop_emb,   // [N, SE]
    const float* __restrict__ week_emb,   // [NW, E]
    const float* __restrict__ conv_b,     // [N]
    const float* __restrict__ fc1_w,      // [L]
    const float* __restrict__ fc1_b,      // scalar
    float*       __restrict__ out)        // [B, N]
{
    __shared__ float s_w[L_];
    __shared__ float s_sh[NSH];
    __shared__ float s_red[8];
    __shared__ float s_base[N_];   // row-independent part of logits
    __shared__ float s_acc[N_];    // streamed accumulator stash

    const int tid  = threadIdx.x;
    const int lane = tid & 31;
    const int warp = tid >> 5;
    const int b    = blockIdx.x;
    const int n0   = tid * 4;
    const bool streamFirst = ((blockIdx.x & 1) == 0);

    if (tid < L_) s_w[tid] = fc1_w[tid];
    // odd blocks gather now (hidden under evens' streaming); evens gather later
    if (!streamFirst)
        gather_sh(b, tid, s_sh, x_features, stops, x_week, stop_emb, week_emb);
    __syncthreads();

    // odd blocks: phase A before streaming
    if (!streamFirst)
        phase_a(b, n0, s_sh, s_base, x_dist, x_markov, conv_b, fc1_b);

    // ---- x stream (R5 pattern) ----
    {
        const float4* xb = (const float4*)(x + (size_t)b * (L_ * N_)) + tid;
        float4 acc = make_float4(0.f, 0.f, 0.f, 0.f);
        #pragma unroll 4
        for (int l = 0; l < L_; ++l) {
            float4 xv = xb[(size_t)l * (N_ / 4)];
            float wl = s_w[l];
            acc.x = fmaf(wl, xv.x, acc.x);
            acc.y = fmaf(wl, xv.y, acc.y);
            acc.z = fmaf(wl, xv.z, acc.z);
            acc.w = fmaf(wl, xv.w, acc.w);
        }
        *(float4*)(&s_acc[n0]) = acc;   // free acc regs across phase A
    }

    // even blocks: gather + phase A after streaming
    if (streamFirst) {
        gather_sh(b, tid, s_sh, x_features, stops, x_week, stop_emb, week_emb);
        __syncthreads();
        phase_a(b, n0, s_sh, s_base, x_dist, x_markov, conv_b, fc1_b);
    }

    // ---- logits + log_softmax + mask + store ----
    {
        float4 acc = *(const float4*)(&s_acc[n0]);     // own entries, no sync needed
        float4 sb  = *(const float4*)(&s_base[n0]);
        float4 w56 = *(const float4*)(&g_tail[0 * N_ + n0]);  // L2-resident

        float lg0 = sb.x + acc.x * w56.x;
        float lg1 = sb.y + acc.y * w56.y;
        float lg2 = sb.z + acc.z * w56.z;
        float lg3 = sb.w + acc.w * w56.w;

        float m = fmaxf(fmaxf(lg0, lg1), fmaxf(lg2, lg3));
        #pragma unroll
        for (int off = 16; off > 0; off >>= 1)
            m = fmaxf(m, __shfl_xor_sync(0xffffffffu, m, off));
        if (lane == 0) s_red[warp] = m;
        __syncthreads();
        m = s_red[0];
        #pragma unroll
        for (int w = 1; w < 8; ++w) m = fmaxf(m, s_red[w]);
        __syncthreads();

        float s = __expf(lg0 - m) + __expf(lg1 - m) + __expf(lg2 - m) + __expf(lg3 - m);
        #pragma unroll
        for (int off = 16; off > 0; off >>= 1)
            s += __shfl_xor_sync(0xffffffffu, s, off);
        if (lane == 0) s_red[warp] = s;
        __syncthreads();
        s = 0.f;
        #pragma unroll
        for (int w = 0; w < 8; ++w) s += s_red[w];
        float lse = m + __logf(s);

        size_t gb = (size_t)b * N_ + (size_t)n0;
        int4 mk = *(const int4*)(&x_mask[gb]);
        float4 o;
        o.x = mk.x ? -1e8f : (lg0 - lse);
        o.y = mk.y ? -1e8f : (lg1 - lse);
        o.z = mk.z ? -1e8f : (lg2 - lse);
        o.w = mk.w ? -1e8f : (lg3 - lse);
        *(float4*)(&out[gb]) = o;
    }
}

extern "C" void kernel_launch(void* const* d_in, const int* in_sizes, int n_in,
                              void* d_out, int out_size) {
    const float* x          = (const float*)d_in[0];
    const float* x_dist     = (const float*)d_in[1];
    const float* x_features = (const float*)d_in[2];
    const float* x_markov   = (const float*)d_in[3];
    const int*   stops      = (const int*)  d_in[4];
    const int*   x_week     = (const int*)  d_in[5];
    const int*   x_mask     = (const int*)  d_in[6];
    const float* stop_emb   = (const float*)d_in[7];
    const float* week_emb   = (const float*)d_in[8];
    const float* conv_w     = (const float*)d_in[9];
    const float* conv_b     = (const float*)d_in[10];
    const float* fc1_w      = (const float*)d_in[11];
    const float* fc1_b      = (const float*)d_in[12];
    float*       out        = (float*)d_out;

    prep_kernel<<<(NF * N_) / T, T>>>(conv_w);
    main_kernel<<<B_, T>>>(x, x_dist, x_features, x_markov, stops, x_week,
                           x_mask, stop_emb, week_emb, conv_b,
                           fc1_w, fc1_b, out);
}

// round 17
// speedup vs baseline: 1.0694x; 1.0033x over previous
#include <cuda_runtime.h>
#include <cuda_fp16.h>
#include <cuda_fp8.h>

#define B_   2048
#define L_   64
#define N_   1024
#define E_   32
#define SE_  16
#define F_   8
#define NSH  56      // E + F + SE
#define NF   59      // NSH + 3
#define S_   20
#define T    256
#define JP   (NSH / 2)   // 28 j-pairs

// fp8 conv weights, packed j-pairs: g_convT8[jp][n][2] = {w[2jp][n], w[2jp+1][n]}  (56 KB)
__device__ __align__(256) __nv_fp8_storage_t g_convT8[JP * N_ * 2];
// fp32 tail rows 56..58 of conv_w (transposed): [w56 | w57 | w58]
__device__ __align__(256) float g_tail[3 * N_];

// prep: conv_w transpose/convert only (236 blocks x 256 == NF*N_ exactly)
__global__ __launch_bounds__(T) void prep_kernel(const float* __restrict__ conv_w)
{
    const int t = blockIdx.x * blockDim.x + threadIdx.x;
    int n = t / NF;
    int j = t - n * NF;
    float v = conv_w[t];
    if (j < NSH)
        g_convT8[(j >> 1) * (N_ * 2) + n * 2 + (j & 1)] =
            __nv_cvt_float_to_fp8(v, __NV_SATFINITE, __NV_E4M3);
    else
        g_tail[(j - NSH) * N_ + n] = v;
}

// single-row phase A: conv dot + row-independent terms -> s_base
__device__ __forceinline__ void phase_a(
    int b, int n0, const float* s_sh, float* s_base,
    const float* __restrict__ x_dist, const float* __restrict__ x_markov,
    const float* __restrict__ conv_b, const float* __restrict__ fc1_b)
{
    float d0 = 0.f, d1 = 0.f, d2 = 0.f, d3 = 0.f;
    #pragma unroll 7
    for (int jp = 0; jp < JP; ++jp) {
        uint2 wv = *(const uint2*)(&g_convT8[jp * (N_ * 2) + n0 * 2]);
        __half2_raw h0 = __nv_cvt_fp8x2_to_halfraw2(
            (__nv_fp8x2_storage_t)(wv.x & 0xFFFFu), __NV_E4M3);
        __half2_raw h1 = __nv_cvt_fp8x2_to_halfraw2(
            (__nv_fp8x2_storage_t)(wv.x >> 16), __NV_E4M3);
        __half2_raw h2 = __nv_cvt_fp8x2_to_halfraw2(
            (__nv_fp8x2_storage_t)(wv.y & 0xFFFFu), __NV_E4M3);
        __half2_raw h3 = __nv_cvt_fp8x2_to_halfraw2(
            (__nv_fp8x2_storage_t)(wv.y >> 16), __NV_E4M3);
        float2 f0 = __half22float2(*(const __half2*)&h0);
        float2 f1 = __half22float2(*(const __half2*)&h1);
        float2 f2 = __half22float2(*(const __half2*)&h2);
        float2 f3 = __half22float2(*(const __half2*)&h3);
        float ha = s_sh[2 * jp], hb = s_sh[2 * jp + 1];
        d0 = fmaf(ha, f0.x, fmaf(hb, f0.y, d0));
        d1 = fmaf(ha, f1.x, fmaf(hb, f1.y, d1));
        d2 = fmaf(ha, f2.x, fmaf(hb, f2.y, d2));
        d3 = fmaf(ha, f3.x, fmaf(hb, f3.y, d3));
    }

    float4 w56 = *(const float4*)(&g_tail[0 * N_ + n0]);
    float4 w57 = *(const float4*)(&g_tail[1 * N_ + n0]);
    float4 w58 = *(const float4*)(&g_tail[2 * N_ + n0]);
    float4 cb  = *(const float4*)(&conv_b[n0]);
    float4 xd  = *(const float4*)(&x_dist[n0]);
    float  fb  = *fc1_b;

    size_t gbase = (size_t)b * N_ + (size_t)n0;
    float4 xm = *(const float4*)(&x_markov[gbase]);

    float4 sb;
    sb.x = d0 + xm.x * w58.x + xd.x * w57.x + cb.x + fb * w56.x;
    sb.y = d1 + xm.y * w58.y + xd.y * w57.y + cb.y + fb * w56.y;
    sb.z = d2 + xm.z * w58.z + xd.z * w57.z + cb.z + fb * w56.z;
    sb.w = d3 + xm.w * w58.w + xd.w * w57.w + cb.w + fb * w56.w;
    *(float4*)(&s_base[n0]) = sb;
}

// this row's shared features -> s_sh
__device__ __forceinline__ void gather_sh(
    int b, int tid, float* s_sh,
    const float* __restrict__ x_features, const int* __restrict__ stops,
    const int* __restrict__ x_week, const float* __restrict__ stop_emb,
    const float* __restrict__ week_emb)
{
    if (tid < NSH) {
        int j = tid;
        float v;
        if (j < E_) {
            v = week_emb[x_week[b] * E_ + j];
        } else if (j < E_ + F_) {
            v = x_features[b * F_ + (j - E_)];
        } else {
            int c = j - E_ - F_;
            float s = 0.f;
            #pragma unroll
            for (int st = 0; st < S_; ++st)
                s += stop_emb[stops[b * S_ + st] * SE_ + c];
            v = s;
        }
        s_sh[j] = v;
    }
}

// fused 1-row kernel, parity-staggered; trimmed epilogue
__global__ __launch_bounds__(T, 8) void main_kernel(
    const float* __restrict__ x,          // [B, L, N]
    const float* __restrict__ x_dist,     // [N]
    const float* __restrict__ x_features, // [B, F]
    const float* __restrict__ x_markov,   // [B, N]
    const int*   __restrict__ stops,      // [B, S]
    const int*   __restrict__ x_week,     // [B]
    const int*   __restrict__ x_mask,     // [B, N]
    const float* __restrict__ stop_emb,   // [N, SE]
    const float* __restrict__ week_emb,   // [NW, E]
    const float* __restrict__ conv_b,     // [N]
    const float* __restrict__ fc1_w,      // [L]
    const float* __restrict__ fc1_b,      // scalar
    float*       __restrict__ out)        // [B, N]
{
    __shared__ float s_w[L_];
    __shared__ float s_sh[NSH];
    __shared__ float s_red_m[8];
    __shared__ float s_red_s[8];
    __shared__ float s_base[N_];   // row-independent part of logits
    __shared__ float s_acc[N_];    // streamed accumulator stash

    const int tid  = threadIdx.x;
    const int lane = tid & 31;
    const int warp = tid >> 5;
    const int b    = blockIdx.x;
    const int n0   = tid * 4;
    const bool streamFirst = ((blockIdx.x & 1) == 0);

    if (tid < L_) s_w[tid] = fc1_w[tid];
    // odd blocks gather now (hidden under evens' streaming); evens gather later
    if (!streamFirst)
        gather_sh(b, tid, s_sh, x_features, stops, x_week, stop_emb, week_emb);
    __syncthreads();

    // odd blocks: phase A before streaming
    if (!streamFirst)
        phase_a(b, n0, s_sh, s_base, x_dist, x_markov, conv_b, fc1_b);

    // ---- x stream (R5 pattern) ----
    {
        const float4* xb = (const float4*)(x + (size_t)b * (L_ * N_)) + tid;
        float4 acc = make_float4(0.f, 0.f, 0.f, 0.f);
        #pragma unroll 4
        for (int l = 0; l < L_; ++l) {
            float4 xv = xb[(size_t)l * (N_ / 4)];
            float wl = s_w[l];
            acc.x = fmaf(wl, xv.x, acc.x);
            acc.y = fmaf(wl, xv.y, acc.y);
            acc.z = fmaf(wl, xv.z, acc.z);
            acc.w = fmaf(wl, xv.w, acc.w);
        }
        *(float4*)(&s_acc[n0]) = acc;   // free acc regs across phase A
    }

    // even blocks: gather + phase A after streaming
    if (streamFirst) {
        gather_sh(b, tid, s_sh, x_features, stops, x_week, stop_emb, week_emb);
        __syncthreads();
        phase_a(b, n0, s_sh, s_base, x_dist, x_markov, conv_b, fc1_b);
    }

    // ---- logits + log_softmax + mask + store ----
    {
        const size_t gb = (size_t)b * N_ + (size_t)n0;
        int4 mk = *(const int4*)(&x_mask[gb]);   // hoisted: hides under reductions

        float4 acc = *(const float4*)(&s_acc[n0]);     // own entries, no sync needed
        float4 sb  = *(const float4*)(&s_base[n0]);
        float4 w56 = *(const float4*)(&g_tail[0 * N_ + n0]);  // L2-resident

        float lg0 = sb.x + acc.x * w56.x;
        float lg1 = sb.y + acc.y * w56.y;
        float lg2 = sb.z + acc.z * w56.z;
        float lg3 = sb.w + acc.w * w56.w;

        float m = fmaxf(fmaxf(lg0, lg1), fmaxf(lg2, lg3));
        #pragma unroll
        for (int off = 16; off > 0; off >>= 1)
            m = fmaxf(m, __shfl_xor_sync(0xffffffffu, m, off));
        if (lane == 0) s_red_m[warp] = m;
        __syncthreads();
        m = s_red_m[0];
        #pragma unroll
        for (int w = 1; w < 8; ++w) m = fmaxf(m, s_red_m[w]);

        float s = __expf(lg0 - m) + __expf(lg1 - m) + __expf(lg2 - m) + __expf(lg3 - m);
        #pragma unroll
        for (int off = 16; off > 0; off >>= 1)
            s += __shfl_xor_sync(0xffffffffu, s, off);
        if (lane == 0) s_red_s[warp] = s;
        __syncthreads();
        s = 0.f;
        #pragma unroll
        for (int w = 0; w < 8; ++w) s += s_red_s[w];
        float lse = m + __logf(s);

        float4 o;
        o.x = mk.x ? -1e8f : (lg0 - lse);
        o.y = mk.y ? -1e8f : (lg1 - lse);
        o.z = mk.z ? -1e8f : (lg2 - lse);
        o.w = mk.w ? -1e8f : (lg3 - lse);
        __stwt((float4*)(&out[gb]), o);
    }
}

extern "C" void kernel_launch(void* const* d_in, const int* in_sizes, int n_in,
                              void* d_out, int out_size) {
    const float* x          = (const float*)d_in[0];
    const float* x_dist     = (const float*)d_in[1];
    const float* x_features = (const float*)d_in[2];
    const float* x_markov   = (const float*)d_in[3];
    const int*   stops      = (const int*)  d_in[4];
    const int*   x_week     = (const int*)  d_in[5];
    const int*   x_mask     = (const int*)  d_in[6];
    const float* stop_emb   = (const float*)d_in[7];
    const float* week_emb   = (const float*)d_in[8];
    const float* conv_w     = (const float*)d_in[9];
    const float* conv_b     = (const float*)d_in[10];
    const float* fc1_w      = (const float*)d_in[11];
    const float* fc1_b      = (const float*)d_in[12];
    float*       out        = (float*)d_out;

    prep_kernel<<<(NF * N_) / T, T>>>(conv_w);
    main_kernel<<<B_, T>>>(x, x_dist, x_features, x_markov, stops, x_week,
                           x_mask, stop_emb, week_emb, conv_b,
                           fc1_w, fc1_b, out);
}